// round 16
// baseline (speedup 1.0000x reference)
#include <cuda_runtime.h>

// BeliefMatchingLoss: pred [8,19,512,512] f32, target [8,512,512] int32 -> scalar f32
// Single-kernel last-block reduction; self-resetting for graph replay.
//
// loss_pix = 0.01*kl + psi(a0) - psi(a_ans)
// kl = lnG(a0) - (a0-19)*psi(a0) + sum_c g(a_c),  a_c = exp(p_c), a0 = sum a_c
// Per-class g via shift-1 (z=x+1, u=1/z, r=1/(x*z), w=x*z=fma(x,x,x)):
//   g ~= p + 1/x + z - 1.5*ln z + (5/6)u + (1/6)u^2 + u^3/90 - (C+1.5)
// Identities: 1/x = u + r (exact) -> fold into poly (5/6 -> 11/6);
//   sum ln z = LN2*sum lg2(W_grp) - sum p  (W_grp = prod(x*z), formed anyway
//   for group-batched reciprocals; sum p accumulated exactly from logits);
//   u^3/90 folded into the u^2 coefficient (1/6 + 1/150).
// Memory: 19 LDG.64 staged via cp.async (one commit group per class), compute
// drafts behind the load stream with wait_group(18-c). Packed 2 px/thread (f32x2).
// This is the best-measured configuration (37.4us) + w=fma(x,x,x) + ballot count.

typedef unsigned long long u64;

#define HW_   (512 * 512)
#define NC_   19
#define NPIX_ (8 * HW_)
#define NTHR_ (NPIX_ / 2)
#define NBLK_ (NTHR_ / 256)

#define LN2F        0.6931471805599453f
#define LOG2EF      1.4426950408889634f
#define HALF_LN_2PI 0.91893853320467274f

__device__ double             g_sum    = 0.0;
__device__ unsigned long long g_cnt    = 0ull;
__device__ unsigned int       g_arrive = 0u;

// ---- packed f32x2 helpers (u64 = {lo,hi} fp32 pair) ----
__device__ __forceinline__ u64 pk2(float a, float b) {
    u64 r; asm("mov.b64 %0,{%1,%2};" : "=l"(r) : "f"(a), "f"(b)); return r;
}
__device__ __forceinline__ void upk2(u64 v, float& a, float& b) {
    asm("mov.b64 {%0,%1},%2;" : "=f"(a), "=f"(b) : "l"(v));
}
__device__ __forceinline__ u64 f2fma(u64 a, u64 b, u64 c) {
    u64 d; asm("fma.rn.f32x2 %0,%1,%2,%3;" : "=l"(d) : "l"(a), "l"(b), "l"(c)); return d;
}
__device__ __forceinline__ u64 f2mul(u64 a, u64 b) {
    u64 d; asm("mul.rn.f32x2 %0,%1,%2;" : "=l"(d) : "l"(a), "l"(b)); return d;
}
__device__ __forceinline__ u64 f2add(u64 a, u64 b) {
    u64 d; asm("add.rn.f32x2 %0,%1,%2;" : "=l"(d) : "l"(a), "l"(b)); return d;
}
__device__ __forceinline__ float ex2f(float x) { float r; asm("ex2.approx.f32 %0,%1;" : "=f"(r) : "f"(x)); return r; }
__device__ __forceinline__ float lg2f_(float x){ float r; asm("lg2.approx.f32 %0,%1;" : "=f"(r) : "f"(x)); return r; }
__device__ __forceinline__ float rcpf_(float x){ float r; asm("rcp.approx.f32 %0,%1;" : "=f"(r) : "f"(x)); return r; }
__device__ __forceinline__ u64 rcp_2(u64 v) { float a, b; upk2(v, a, b); return pk2(rcpf_(a), rcpf_(b)); }

// scalar digamma+lgamma, shift-2 (accurate; once per pixel on a0 >= ~5)
__device__ __forceinline__ void psi_lg_s(float x, float& psi, float& lg) {
    float z   = x + 2.0f;
    float P   = fmaf(x, x, x);
    float r   = rcpf_(P * z);
    float S   = fmaf(2.0f, P, fmaf(3.0f, x, 2.0f)) * r;
    float rz  = P * r;
    float rz2 = rz * rz;
    float lnz = lg2f_(z) * LN2F;
    float lnP = lg2f_(P) * LN2F;
    float c = fmaf(rz, 0.5f, rz2 * fmaf(rz2, -1.0f / 120.0f, 1.0f / 12.0f));
    float t = rz * fmaf(rz2, -1.0f / 360.0f, 1.0f / 12.0f);
    psi = lnz - c - S;
    lg  = fmaf(z - 0.5f, lnz, -z) + HALF_LN_2PI + t - lnP;
}

// scalar digamma only, shift-2 (once per pixel on x_ans)
__device__ __forceinline__ float psi_s(float x) {
    float z   = x + 2.0f;
    float P   = fmaf(x, x, x);
    float r   = rcpf_(P * z);
    float S   = fmaf(2.0f, P, fmaf(3.0f, x, 2.0f)) * r;
    float rz  = P * r;
    float rz2 = rz * rz;
    float c = fmaf(rz, 0.5f, rz2 * fmaf(rz2, -1.0f / 120.0f, 1.0f / 12.0f));
    return lg2f_(z) * LN2F - c - S;
}

__global__ __launch_bounds__(256, 5) void bml_main(const float* __restrict__ pred,
                                                   const int*  __restrict__ tgt,
                                                   float*      __restrict__ out) {
    __shared__ u64 smq[NC_ * 256];   // 38912 B: per-thread staging, slot [c*256 + tid]

    unsigned tid = threadIdx.x;
    int tix = blockIdx.x * 256 + (int)tid;
    int pix = tix * 2;
    int b   = pix >> 18;
    int hw  = pix & (HW_ - 1);
    const float* pp = pred + (size_t)b * NC_ * HW_ + hw;

    unsigned sbase;
    asm("{ .reg .u64 t; cvta.to.shared.u64 t, %1; cvt.u32.u64 %0, t; }"
        : "=r"(sbase) : "l"(smq));
    unsigned stid = sbase + tid * 8u;

    // ---- issue all 19 staged loads, one commit group per class ----
#define CPA(c) asm volatile( \
        "cp.async.ca.shared.global [%0], [%1], 8;\n\t" \
        "cp.async.commit_group;" \
        :: "r"(stid + (unsigned)((c) * 2048)), "l"(pp + (size_t)(c) * HW_) : "memory")
    CPA(0);  CPA(1);  CPA(2);  CPA(3);  CPA(4);  CPA(5);  CPA(6);
    CPA(7);  CPA(8);  CPA(9);  CPA(10); CPA(11); CPA(12); CPA(13);
    CPA(14); CPA(15); CPA(16); CPA(17); CPA(18);
#undef CPA

    int2 tv  = *reinterpret_cast<const int2*>(tgt + pix);
    bool ig0 = (tv.x == 255), ig1 = (tv.y == 255);
    int  ta0 = ig0 ? 0 : tv.x;
    int  ta1 = ig1 ? 0 : tv.y;

    const u64 KL2E = pk2(LOG2EF, LOG2EF);
    const u64 Ca   = pk2(11.0f / 6.0f, 11.0f / 6.0f);   // 5/6 + 1 (1/x fold)
    const u64 Cb   = pk2(0.17333333f, 0.17333333f);     // 1/6 + 1/150 (u^3 fold)

    u64 accU = pk2(0.0f, 0.0f);   // sum u*(Ca + Cb*u)
    u64 accR = accU;              // sum r  (r = 1/(x z))
    u64 accP = accU;              // sum p  (= sum ln x, exact)
    u64 a0v  = accU;              // sum x
    float lgw_lo = 0.0f, lgw_hi = 0.0f;  // sum lg2(W_group), W = prod x*z

#define LOADC(pv, c) do {                                                     \
        asm volatile("cp.async.wait_group %0;" :: "n"(18 - (c)) : "memory");  \
        asm volatile("ld.shared.b64 %0,[%1];"                                 \
                     : "=l"(pv) : "r"(stid + (unsigned)((c) * 2048)));        \
    } while (0)

#define STAGE1(xx, ww, c) do {                                                \
        u64 pv; LOADC(pv, c);                                                 \
        accP = f2add(accP, pv);                                               \
        u64 e  = f2mul(pv, KL2E);                                             \
        float el, eh; upk2(e, el, eh);                                        \
        (xx) = pk2(ex2f(el), ex2f(eh));                                       \
        (ww) = f2fma((xx), (xx), (xx));                                       \
    } while (0)

#define STAGE2(xx, rr) do {                                                   \
        u64 u_ = f2mul((xx), (rr));                                           \
        u64 q  = f2fma(u_, Cb, Ca);                                           \
        accU   = f2fma(u_, q, accU);                                          \
        accR   = f2add(accR, (rr));                                           \
        a0v    = f2add(a0v, (xx));                                            \
    } while (0)

    // groups of 4 classes: one RCP (of W-product) and one LG2 per pixel
#define GROUP4(c0) do {                                                       \
        u64 x0, w0, x1, w1, x2, w2, x3, w3;                                   \
        STAGE1(x0, w0, (c0) + 0);                                             \
        STAGE1(x1, w1, (c0) + 1);                                             \
        STAGE1(x2, w2, (c0) + 2);                                             \
        STAGE1(x3, w3, (c0) + 3);                                             \
        u64 Wab = f2mul(w0, w1);                                              \
        u64 Wcd = f2mul(w2, w3);                                              \
        u64 Wq  = f2mul(Wab, Wcd);                                            \
        float wl, wh; upk2(Wq, wl, wh);                                       \
        lgw_lo += lg2f_(wl); lgw_hi += lg2f_(wh);                             \
        u64 rr  = rcp_2(Wq);                                                  \
        u64 rab = f2mul(rr, Wcd);                                             \
        u64 rcd = f2mul(rr, Wab);                                             \
        STAGE2(x0, f2mul(rab, w1));                                           \
        STAGE2(x1, f2mul(rab, w0));                                           \
        STAGE2(x2, f2mul(rcd, w3));                                           \
        STAGE2(x3, f2mul(rcd, w2));                                           \
    } while (0)

    GROUP4(0); GROUP4(4); GROUP4(8); GROUP4(12);
    { // tail group of 3 (classes 16,17,18)
        u64 x0, w0, x1, w1, x2, w2;
        STAGE1(x0, w0, 16);
        STAGE1(x1, w1, 17);
        STAGE1(x2, w2, 18);
        u64 Wab = f2mul(w0, w1);
        u64 Wq  = f2mul(Wab, w2);
        float wl, wh; upk2(Wq, wl, wh);
        lgw_lo += lg2f_(wl); lgw_hi += lg2f_(wh);
        u64 rr  = rcp_2(Wq);
        u64 rab = f2mul(rr, w2);
        STAGE2(x0, f2mul(rab, w1));
        STAGE2(x1, f2mul(rab, w0));
        STAGE2(x2, f2mul(rr, Wab));
    }
#undef GROUP4
#undef STAGE1
#undef STAGE2
#undef LOADC

    // answer-class logits from smem (all groups complete)
    float pa0, pa1;
    asm volatile("ld.shared.f32 %0,[%1];"
                 : "=f"(pa0) : "r"(stid + (unsigned)ta0 * 2048u));
    asm volatile("ld.shared.f32 %0,[%1];"
                 : "=f"(pa1) : "r"(stid + (unsigned)ta1 * 2048u + 4u));

    float aU_lo, aU_hi, aR_lo, aR_hi, aP_lo, aP_hi, a0_lo, a0_hi;
    upk2(accU, aU_lo, aU_hi);
    upk2(accR, aR_lo, aR_hi);
    upk2(accP, aP_lo, aP_hi);
    upk2(a0v,  a0_lo, a0_hi);

    // sum_g = 2.5*sum_p + accR + accU + a0 - 1.5*LN2*lgw + KADD
    const float KADD = 19.0f * (1.0f - 1.5f - HALF_LN_2PI);

    float xa0 = ex2f(pa0 * LOG2EF);
    float xa1 = ex2f(pa1 * LOG2EF);

    float sumg_lo = fmaf(2.5f, aP_lo, fmaf(-1.5f * LN2F, lgw_lo, aR_lo + aU_lo)) + a0_lo + KADD;
    float psi0_lo, lg0_lo;
    psi_lg_s(a0_lo, psi0_lo, lg0_lo);
    float kl_lo   = fmaf(-(a0_lo - 19.0f), psi0_lo, lg0_lo) + sumg_lo;
    float loss_lo = fmaf(0.01f, kl_lo, psi0_lo - psi_s(xa0));
    if (ig0) loss_lo = 0.0f;

    float sumg_hi = fmaf(2.5f, aP_hi, fmaf(-1.5f * LN2F, lgw_hi, aR_hi + aU_hi)) + a0_hi + KADD;
    float psi0_hi, lg0_hi;
    psi_lg_s(a0_hi, psi0_hi, lg0_hi);
    float kl_hi   = fmaf(-(a0_hi - 19.0f), psi0_hi, lg0_hi) + sumg_hi;
    float loss_hi = fmaf(0.01f, kl_hi, psi0_hi - psi_s(xa1));
    if (ig1) loss_hi = 0.0f;

    float loss = loss_lo + loss_hi;

    unsigned m0 = __ballot_sync(0xffffffffu, ig0);
    unsigned m1 = __ballot_sync(0xffffffffu, ig1);
    int valid_w = 64 - __popc(m0) - __popc(m1);

#pragma unroll
    for (int o = 16; o; o >>= 1)
        loss += __shfl_down_sync(0xffffffffu, loss, o);

    __shared__ float s_l[8];
    __shared__ int   s_v[8];
    int wid = threadIdx.x >> 5;
    int lid = threadIdx.x & 31;
    if (lid == 0) { s_l[wid] = loss; s_v[wid] = valid_w; }
    __syncthreads();

    if (threadIdx.x == 0) {
        float L = 0.0f;
        int   V = 0;
#pragma unroll
        for (int w = 0; w < 8; ++w) { L += s_l[w]; V += s_v[w]; }
        atomicAdd(&g_sum, (double)L);
        atomicAdd(&g_cnt, (unsigned long long)V);
        __threadfence();
        unsigned int n = atomicAdd(&g_arrive, 1u);
        if (n == (unsigned int)(NBLK_ - 1)) {
            __threadfence();
            double s = *((volatile double*)&g_sum);
            unsigned long long c = *((volatile unsigned long long*)&g_cnt);
            out[0] = (float)(s / (double)c);
            g_sum    = 0.0;
            g_cnt    = 0ull;
            g_arrive = 0u;
        }
    }
}

extern "C" void kernel_launch(void* const* d_in, const int* in_sizes, int n_in,
                              void* d_out, int out_size) {
    const float* pred = (const float*)d_in[0];
    const int*   tgt  = (const int*)d_in[1];
    float*       out  = (float*)d_out;

    bml_main<<<NBLK_, 256>>>(pred, tgt, out);
}

// round 17
// speedup vs baseline: 1.4306x; 1.4306x over previous
#include <cuda_runtime.h>

// BeliefMatchingLoss: pred [8,19,512,512] f32, target [8,512,512] int32 -> scalar f32
// Single-kernel last-block reduction; self-resetting for graph replay.
//
// loss_pix = 0.01*kl + psi(a0) - psi(a_ans)
// kl = lnG(a0) - (a0-19)*psi(a0) + sum_c g(a_c),  a_c = exp(p_c), a0 = sum a_c
// Per-class g via shift-1 (z=x+1, u=1/z, r=1/(x*z), w=x*z=fma(x,x,x)):
//   g ~= p + 1/x + z - 1.5*ln z + (5/6)u + (1/6)u^2 + u^3/90 - (C+1.5)
// Identities: 1/x = u + r (exact, folds into poly), sum ln z = LN2*lg2(prod w) - sum p.
// Memory: 19 LDG.64 staged via cp.async, one commit group per 4-class quad,
// one wait per quad so compute drafts one quad behind the load stream.
// ALL math (main loop + epilogue) packed 2 px/thread via f32x2.
// (Best-measured-per-clock configuration; w=fma(x,x,x) is the only delta.)

typedef unsigned long long u64;

#define HW_   (512 * 512)
#define NC_   19
#define NPIX_ (8 * HW_)
#define NTHR_ (NPIX_ / 2)
#define NBLK_ (NTHR_ / 256)

#define LN2F        0.6931471805599453f
#define LOG2EF      1.4426950408889634f
#define HALF_LN_2PI 0.91893853320467274f

__device__ double             g_sum    = 0.0;
__device__ unsigned long long g_cnt    = 0ull;
__device__ unsigned int       g_arrive = 0u;

// ---- packed f32x2 helpers (u64 = {lo,hi} fp32 pair) ----
__device__ __forceinline__ u64 pk2(float a, float b) {
    u64 r; asm("mov.b64 %0,{%1,%2};" : "=l"(r) : "f"(a), "f"(b)); return r;
}
__device__ __forceinline__ void upk2(u64 v, float& a, float& b) {
    asm("mov.b64 {%0,%1},%2;" : "=f"(a), "=f"(b) : "l"(v));
}
__device__ __forceinline__ u64 f2fma(u64 a, u64 b, u64 c) {
    u64 d; asm("fma.rn.f32x2 %0,%1,%2,%3;" : "=l"(d) : "l"(a), "l"(b), "l"(c)); return d;
}
__device__ __forceinline__ u64 f2mul(u64 a, u64 b) {
    u64 d; asm("mul.rn.f32x2 %0,%1,%2;" : "=l"(d) : "l"(a), "l"(b)); return d;
}
__device__ __forceinline__ u64 f2add(u64 a, u64 b) {
    u64 d; asm("add.rn.f32x2 %0,%1,%2;" : "=l"(d) : "l"(a), "l"(b)); return d;
}
__device__ __forceinline__ u64 f2sub(u64 a, u64 b) {
    return f2fma(b, pk2(-1.0f, -1.0f), a);
}
__device__ __forceinline__ float ex2f(float x) { float r; asm("ex2.approx.f32 %0,%1;" : "=f"(r) : "f"(x)); return r; }
__device__ __forceinline__ float lg2f_(float x){ float r; asm("lg2.approx.f32 %0,%1;" : "=f"(r) : "f"(x)); return r; }
__device__ __forceinline__ float rcpf_(float x){ float r; asm("rcp.approx.f32 %0,%1;" : "=f"(r) : "f"(x)); return r; }
__device__ __forceinline__ u64 rcp_2(u64 v) { float a, b; upk2(v, a, b); return pk2(rcpf_(a), rcpf_(b)); }
__device__ __forceinline__ u64 lg2_2(u64 v) { float a, b; upk2(v, a, b); return pk2(lg2f_(a), lg2f_(b)); }

// packed epilogue: psi+lnG at a0 (shift-2), psi at x_ans, combine both pixels
__device__ __forceinline__ u64 lane_loss(u64 a0v, u64 accP, u64 accR, u64 accU,
                                         u64 lgw, u64 xa) {
    const u64 K2p   = pk2(2.0f, 2.0f);
    const u64 K3p   = pk2(3.0f, 3.0f);
    const u64 KHp   = pk2(0.5f, 0.5f);
    const u64 K12p  = pk2(1.0f / 12.0f, 1.0f / 12.0f);
    const u64 Km120 = pk2(-1.0f / 120.0f, -1.0f / 120.0f);
    const u64 Km360 = pk2(-1.0f / 360.0f, -1.0f / 360.0f);
    const u64 KLN2  = pk2(LN2F, LN2F);

    // psi0/lg0 at a0
    u64 z0   = f2add(a0v, K2p);
    u64 P0   = f2fma(a0v, a0v, a0v);
    u64 r0   = rcp_2(f2mul(P0, z0));
    u64 S0   = f2mul(f2fma(K2p, P0, f2fma(K3p, a0v, K2p)), r0);
    u64 rz   = f2mul(P0, r0);
    u64 rz2  = f2mul(rz, rz);
    u64 lnz0 = f2mul(lg2_2(z0), KLN2);
    u64 lnP0 = f2mul(lg2_2(P0), KLN2);
    u64 cv   = f2fma(rz, KHp, f2mul(rz2, f2fma(rz2, Km120, K12p)));
    u64 tv_  = f2mul(rz, f2fma(rz2, Km360, K12p));
    u64 psi0 = f2sub(f2sub(lnz0, cv), S0);
    u64 lg0  = f2fma(f2sub(z0, KHp), lnz0, f2sub(tv_, z0));
    lg0 = f2add(f2sub(lg0, lnP0), pk2(HALF_LN_2PI, HALF_LN_2PI));

    // psia at x_ans
    u64 za   = f2add(xa, K2p);
    u64 Pa   = f2fma(xa, xa, xa);
    u64 ra   = rcp_2(f2mul(Pa, za));
    u64 Sa   = f2mul(f2fma(K2p, Pa, f2fma(K3p, xa, K2p)), ra);
    u64 rza  = f2mul(Pa, ra);
    u64 rza2 = f2mul(rza, rza);
    u64 ca   = f2fma(rza, KHp, f2mul(rza2, f2fma(rza2, Km120, K12p)));
    u64 psia = f2sub(f2sub(f2mul(lg2_2(za), KLN2), ca), Sa);

    // sum_g = 2.5*accP - 1.5*LN2*lgw + accR + accU + a0 + KADD
    const float KADDf = 19.0f * (1.0f - 1.5f - HALF_LN_2PI);
    u64 sumg = f2fma(pk2(2.5f, 2.5f), accP,
               f2fma(pk2(-1.5f * LN2F, -1.5f * LN2F), lgw, f2add(accR, accU)));
    sumg = f2add(sumg, f2add(a0v, pk2(KADDf, KADDf)));

    // kl = (19 - a0)*psi0 + lg0 + sumg ; loss = 0.01*kl + psi0 - psia
    u64 kl = f2fma(f2sub(pk2(19.0f, 19.0f), a0v), psi0, f2add(lg0, sumg));
    return f2fma(pk2(0.01f, 0.01f), kl, f2sub(psi0, psia));
}

__global__ __launch_bounds__(256, 5) void bml_main(const float* __restrict__ pred,
                                                   const int*  __restrict__ tgt,
                                                   float*      __restrict__ out) {
    __shared__ u64 smq[NC_ * 256];   // 38912 B staging, slot [c*256 + tid]

    unsigned tid = threadIdx.x;
    int tix = blockIdx.x * 256 + (int)tid;
    int pix = tix * 2;
    int b   = pix >> 18;
    int hw  = pix & (HW_ - 1);
    const float* pp = pred + (size_t)b * NC_ * HW_ + hw;

    unsigned sbase;
    asm("{ .reg .u64 t; cvta.to.shared.u64 t, %1; cvt.u32.u64 %0, t; }"
        : "=r"(sbase) : "l"(smq));
    unsigned stid = sbase + tid * 8u;

    // ---- issue all 19 staged loads; one commit group per 4-class quad ----
#define CPA(c) asm volatile( \
        "cp.async.ca.shared.global [%0], [%1], 8;" \
        :: "r"(stid + (unsigned)((c) * 2048)), "l"(pp + (size_t)(c) * HW_) : "memory")
#define CG() asm volatile("cp.async.commit_group;" ::: "memory")
    CPA(0);  CPA(1);  CPA(2);  CPA(3);  CG();
    CPA(4);  CPA(5);  CPA(6);  CPA(7);  CG();
    CPA(8);  CPA(9);  CPA(10); CPA(11); CG();
    CPA(12); CPA(13); CPA(14); CPA(15); CG();
    CPA(16); CPA(17); CPA(18);          CG();
#undef CPA
#undef CG

    int2 tv  = *reinterpret_cast<const int2*>(tgt + pix);
    bool ig0 = (tv.x == 255), ig1 = (tv.y == 255);
    int  ta0 = ig0 ? 0 : tv.x;
    int  ta1 = ig1 ? 0 : tv.y;

    const u64 KL2E = pk2(LOG2EF, LOG2EF);
    const u64 Ca   = pk2(11.0f / 6.0f, 11.0f / 6.0f);   // 5/6 + 1 (1/x fold)
    const u64 Cb   = pk2(0.17333333f, 0.17333333f);     // 1/6 + 1/150 (u^3 fold)

    u64 accU = pk2(0.0f, 0.0f);   // sum u*(Ca + Cb*u)
    u64 accR = accU;              // sum r  (r = 1/(x z))
    u64 accP = accU;              // sum p  (= sum ln x, exact)
    u64 a0v  = accU;              // sum x
    u64 lgw  = accU;              // sum lg2(W_group), W = prod x*z

#define WAITG(n) asm volatile("cp.async.wait_group %0;" :: "n"(n) : "memory")

#define STAGE1(xx, ww, c) do {                                                \
        u64 pv;                                                               \
        asm volatile("ld.shared.b64 %0,[%1];"                                 \
                     : "=l"(pv) : "r"(stid + (unsigned)((c) * 2048)));        \
        accP = f2add(accP, pv);                                               \
        u64 e  = f2mul(pv, KL2E);                                             \
        float el, eh; upk2(e, el, eh);                                        \
        (xx) = pk2(ex2f(el), ex2f(eh));                                       \
        (ww) = f2fma((xx), (xx), (xx));   /* w = x(x+1) */                    \
    } while (0)

#define STAGE2(xx, rr) do {                                                   \
        u64 u_ = f2mul((xx), (rr));                                           \
        u64 q  = f2fma(u_, Cb, Ca);                                           \
        accU   = f2fma(u_, q, accU);                                          \
        accR   = f2add(accR, (rr));                                           \
        a0v    = f2add(a0v, (xx));                                            \
    } while (0)

#define QUAD(c0, wg) do {                                                     \
        WAITG(wg);                                                            \
        u64 x0, w0, x1, w1, x2, w2, x3, w3;                                   \
        STAGE1(x0, w0, (c0) + 0);                                             \
        STAGE1(x1, w1, (c0) + 1);                                             \
        STAGE1(x2, w2, (c0) + 2);                                             \
        STAGE1(x3, w3, (c0) + 3);                                             \
        u64 Wab = f2mul(w0, w1);                                              \
        u64 Wcd = f2mul(w2, w3);                                              \
        u64 Wq  = f2mul(Wab, Wcd);                                            \
        lgw = f2add(lgw, lg2_2(Wq));                                          \
        u64 rr  = rcp_2(Wq);                                                  \
        u64 rab = f2mul(rr, Wcd);                                             \
        u64 rcd = f2mul(rr, Wab);                                             \
        STAGE2(x0, f2mul(rab, w1));                                           \
        STAGE2(x1, f2mul(rab, w0));                                           \
        STAGE2(x2, f2mul(rcd, w3));                                           \
        STAGE2(x3, f2mul(rcd, w2));                                           \
    } while (0)

    QUAD(0, 4); QUAD(4, 3); QUAD(8, 2); QUAD(12, 1);
    { // tail group of 3 (classes 16,17,18)
        WAITG(0);
        u64 x0, w0, x1, w1, x2, w2;
        STAGE1(x0, w0, 16);
        STAGE1(x1, w1, 17);
        STAGE1(x2, w2, 18);
        u64 Wab = f2mul(w0, w1);
        u64 Wq  = f2mul(Wab, w2);
        lgw = f2add(lgw, lg2_2(Wq));
        u64 rr  = rcp_2(Wq);
        u64 rab = f2mul(rr, w2);
        STAGE2(x0, f2mul(rab, w1));
        STAGE2(x1, f2mul(rab, w0));
        STAGE2(x2, f2mul(rr, Wab));
    }
#undef QUAD
#undef STAGE1
#undef STAGE2
#undef WAITG

    // answer-class logits from smem (all groups complete)
    float pa0, pa1;
    asm volatile("ld.shared.f32 %0,[%1];"
                 : "=f"(pa0) : "r"(stid + (unsigned)ta0 * 2048u));
    asm volatile("ld.shared.f32 %0,[%1];"
                 : "=f"(pa1) : "r"(stid + (unsigned)ta1 * 2048u + 4u));

    u64 xa = pk2(ex2f(pa0 * LOG2EF), ex2f(pa1 * LOG2EF));
    u64 lossp = lane_loss(a0v, accP, accR, accU, lgw, xa);

    float loss_lo, loss_hi;
    upk2(lossp, loss_lo, loss_hi);
    if (ig0) loss_lo = 0.0f;
    if (ig1) loss_hi = 0.0f;
    float loss = loss_lo + loss_hi;

    // valid count via ballot (uniform per warp)
    unsigned m0 = __ballot_sync(0xffffffffu, ig0);
    unsigned m1 = __ballot_sync(0xffffffffu, ig1);
    int valid_w = 64 - __popc(m0) - __popc(m1);

#pragma unroll
    for (int o = 16; o; o >>= 1)
        loss += __shfl_down_sync(0xffffffffu, loss, o);

    __shared__ float s_l[8];
    __shared__ int   s_v[8];
    int wid = threadIdx.x >> 5;
    int lid = threadIdx.x & 31;
    if (lid == 0) { s_l[wid] = loss; s_v[wid] = valid_w; }
    __syncthreads();

    if (threadIdx.x == 0) {
        float L = 0.0f;
        int   V = 0;
#pragma unroll
        for (int w = 0; w < 8; ++w) { L += s_l[w]; V += s_v[w]; }
        atomicAdd(&g_sum, (double)L);
        atomicAdd(&g_cnt, (unsigned long long)V);
        __threadfence();
        unsigned int n = atomicAdd(&g_arrive, 1u);
        if (n == (unsigned int)(NBLK_ - 1)) {
            __threadfence();
            double s = *((volatile double*)&g_sum);
            unsigned long long c = *((volatile unsigned long long*)&g_cnt);
            out[0] = (float)(s / (double)c);
            g_sum    = 0.0;
            g_cnt    = 0ull;
            g_arrive = 0u;
        }
    }
}

extern "C" void kernel_launch(void* const* d_in, const int* in_sizes, int n_in,
                              void* d_out, int out_size) {
    const float* pred = (const float*)d_in[0];
    const int*   tgt  = (const int*)d_in[1];
    float*       out  = (float*)d_out;

    bml_main<<<NBLK_, 256>>>(pred, tgt, out);
}